// round 1
// baseline (speedup 1.0000x reference)
#include <cuda_runtime.h>
#include <cstdint>

#define HID   256
#define NN    4096
#define BATCH 4
#define ROWS  (BATCH*NN)   // 16384
#define KNN   8

// ---- scratch (static device globals; no runtime allocation) ----
__device__ float d_Qg[(size_t)ROWS * HID];              // 16.8 MB
__device__ float d_Kg[(size_t)ROWS * HID];              // 16.8 MB
__device__ float d_Sg[(size_t)BATCH * NN * NN];         // 268 MB
__device__ float d_TopV[ROWS * KNN];
__device__ int   d_TopI[ROWS * KNN];

// ---- packed f32x2 helpers (sm_100+ PTX; ptxas never auto-fuses FFMA2) ----
__device__ __forceinline__ unsigned long long pk2(float lo, float hi) {
    unsigned long long r;
    asm("mov.b64 %0, {%1, %2};" : "=l"(r) : "f"(lo), "f"(hi));
    return r;
}
__device__ __forceinline__ void upk2(unsigned long long v, float& lo, float& hi) {
    asm("mov.b64 {%0, %1}, %2;" : "=f"(lo), "=f"(hi) : "l"(v));
}
__device__ __forceinline__ void fma2(unsigned long long& d,
                                     unsigned long long a, unsigned long long b) {
    asm("fma.rn.f32x2 %0, %1, %2, %0;" : "+l"(d) : "l"(a), "l"(b));
}

// ============================================================================
// C[M,N] = scale * (A[M,K] @ B[N,K]^T) (+ bias[N]); batched via blockIdx.z.
// 128x128 block tile, BK=16, 256 threads, 8x8 microtile, f32x2 accumulators,
// double-buffered smem with register prefetch.
// ============================================================================
#define BM 128
#define BN 128
#define BK 16
#define TM 8
#define TN 8

__global__ __launch_bounds__(256, 2) void sgemm_tn_kernel(
    const float* __restrict__ A, const float* __restrict__ B, float* __restrict__ C,
    int N, int Kd, long sA, long sB, long sC,
    const float* __restrict__ bias, float scale)
{
    A += (long)blockIdx.z * sA;
    B += (long)blockIdx.z * sB;
    C += (long)blockIdx.z * sC;

    const int tid = threadIdx.x;
    const int tx  = tid & 15;        // 16 col groups
    const int ty  = tid >> 4;        // 16 row groups
    const long bm = (long)blockIdx.y * BM;
    const long bn = (long)blockIdx.x * BN;

    __shared__ float As[2][BK][BM];
    __shared__ float Bs[2][BK][BN];

    unsigned long long acc[TM][TN/2];
#pragma unroll
    for (int i = 0; i < TM; i++)
#pragma unroll
        for (int j = 0; j < TN/2; j++) acc[i][j] = 0ULL;

    // loader: each thread fetches 8 contiguous floats of one row per matrix
    const int lr = tid >> 1;            // 0..127  (tile row)
    const int lc = (tid & 1) * 8;       // 0 or 8  (k-chunk within BK=16)

    const float* Abase = A + (bm + lr) * Kd + lc;
    const float* Bbase = B + (bn + lr) * Kd + lc;

    float4 ra0, ra1, rb0, rb1;

    // prologue: tile 0
    ra0 = *(const float4*)(Abase);
    ra1 = *(const float4*)(Abase + 4);
    rb0 = *(const float4*)(Bbase);
    rb1 = *(const float4*)(Bbase + 4);
    {
        As[0][lc+0][lr]=ra0.x; As[0][lc+1][lr]=ra0.y; As[0][lc+2][lr]=ra0.z; As[0][lc+3][lr]=ra0.w;
        As[0][lc+4][lr]=ra1.x; As[0][lc+5][lr]=ra1.y; As[0][lc+6][lr]=ra1.z; As[0][lc+7][lr]=ra1.w;
        Bs[0][lc+0][lr]=rb0.x; Bs[0][lc+1][lr]=rb0.y; Bs[0][lc+2][lr]=rb0.z; Bs[0][lc+3][lr]=rb0.w;
        Bs[0][lc+4][lr]=rb1.x; Bs[0][lc+5][lr]=rb1.y; Bs[0][lc+6][lr]=rb1.z; Bs[0][lc+7][lr]=rb1.w;
    }
    __syncthreads();

    const int KT = Kd / BK;
    for (int kt = 0; kt < KT; ++kt) {
        const int buf = kt & 1;
        if (kt + 1 < KT) {
            const float* Ap = Abase + (kt + 1) * BK;
            const float* Bp = Bbase + (kt + 1) * BK;
            ra0 = *(const float4*)(Ap);
            ra1 = *(const float4*)(Ap + 4);
            rb0 = *(const float4*)(Bp);
            rb1 = *(const float4*)(Bp + 4);
        }
#pragma unroll
        for (int kk = 0; kk < BK; kk++) {
            float4 a0 = *(const float4*)&As[buf][kk][ty * TM];
            float4 a1 = *(const float4*)&As[buf][kk][ty * TM + 4];
            ulonglong2 b0 = *(const ulonglong2*)&Bs[buf][kk][tx * TN];
            ulonglong2 b1 = *(const ulonglong2*)&Bs[buf][kk][tx * TN + 4];
            unsigned long long ad[TM] = {
                pk2(a0.x,a0.x), pk2(a0.y,a0.y), pk2(a0.z,a0.z), pk2(a0.w,a0.w),
                pk2(a1.x,a1.x), pk2(a1.y,a1.y), pk2(a1.z,a1.z), pk2(a1.w,a1.w)
            };
            unsigned long long bd[4] = { b0.x, b0.y, b1.x, b1.y };
#pragma unroll
            for (int i = 0; i < TM; i++) {
                fma2(acc[i][0], ad[i], bd[0]);
                fma2(acc[i][1], ad[i], bd[1]);
                fma2(acc[i][2], ad[i], bd[2]);
                fma2(acc[i][3], ad[i], bd[3]);
            }
        }
        if (kt + 1 < KT) {
            const int nb = buf ^ 1;
            As[nb][lc+0][lr]=ra0.x; As[nb][lc+1][lr]=ra0.y; As[nb][lc+2][lr]=ra0.z; As[nb][lc+3][lr]=ra0.w;
            As[nb][lc+4][lr]=ra1.x; As[nb][lc+5][lr]=ra1.y; As[nb][lc+6][lr]=ra1.z; As[nb][lc+7][lr]=ra1.w;
            Bs[nb][lc+0][lr]=rb0.x; Bs[nb][lc+1][lr]=rb0.y; Bs[nb][lc+2][lr]=rb0.z; Bs[nb][lc+3][lr]=rb0.w;
            Bs[nb][lc+4][lr]=rb1.x; Bs[nb][lc+5][lr]=rb1.y; Bs[nb][lc+6][lr]=rb1.z; Bs[nb][lc+7][lr]=rb1.w;
        }
        __syncthreads();
    }

    // epilogue
#pragma unroll
    for (int i = 0; i < TM; i++) {
        const long rrow = bm + ty * TM + i;
        float* Cr = C + rrow * (long)N + bn + tx * TN;
        float o[8];
        upk2(acc[i][0], o[0], o[1]);
        upk2(acc[i][1], o[2], o[3]);
        upk2(acc[i][2], o[4], o[5]);
        upk2(acc[i][3], o[6], o[7]);
        if (bias) {
            const float* bp = bias + bn + tx * TN;
#pragma unroll
            for (int j = 0; j < 8; j++) o[j] = o[j] * scale + bp[j];
        } else {
#pragma unroll
            for (int j = 0; j < 8; j++) o[j] *= scale;
        }
        *(float4*)(Cr)     = make_float4(o[0], o[1], o[2], o[3]);
        *(float4*)(Cr + 4) = make_float4(o[4], o[5], o[6], o[7]);
    }
}

// ============================================================================
// Per-row: max, sum-exp(Z), top-8 (tie -> lowest index), renormalized values.
// out value for top-8 element j: e_j / (E8 + 1e-6 * Z), e_j = exp(s_j - m).
// ============================================================================
__global__ __launch_bounds__(256) void rowtopk_kernel()
{
    const int row = blockIdx.x;
    const float* s = d_Sg + (size_t)row * NN;
    __shared__ float sh[NN];
    __shared__ float rv[256];
    __shared__ int   ri[256];
    const int tid = threadIdx.x;

    for (int i = tid; i < NN/4; i += 256)
        ((float4*)sh)[i] = ((const float4*)s)[i];
    __syncthreads();

    // row max
    float m = -1e30f;
    for (int i = tid; i < NN; i += 256) m = fmaxf(m, sh[i]);
    rv[tid] = m; __syncthreads();
    for (int o = 128; o > 0; o >>= 1) {
        if (tid < o) rv[tid] = fmaxf(rv[tid], rv[tid + o]);
        __syncthreads();
    }
    m = rv[0]; __syncthreads();

    // full softmax denominator Z
    float z = 0.f;
    for (int i = tid; i < NN; i += 256) z += __expf(sh[i] - m);
    rv[tid] = z; __syncthreads();
    for (int o = 128; o > 0; o >>= 1) {
        if (tid < o) rv[tid] += rv[tid + o];
        __syncthreads();
    }
    const float Z = rv[0]; __syncthreads();

    // 8 argmax passes with exclusion
    float tv[KNN]; int tix[KNN];
    float E8 = 0.f;
    for (int k = 0; k < KNN; k++) {
        float bv = -1e30f; int bi = 0x7fffffff;
        for (int i = tid; i < NN; i += 256) {
            float v = sh[i];
            if (v > bv) { bv = v; bi = i; }
        }
        rv[tid] = bv; ri[tid] = bi; __syncthreads();
        for (int o = 128; o > 0; o >>= 1) {
            if (tid < o) {
                float ov = rv[tid + o]; int oi = ri[tid + o];
                if (ov > rv[tid] || (ov == rv[tid] && oi < ri[tid])) {
                    rv[tid] = ov; ri[tid] = oi;
                }
            }
            __syncthreads();
        }
        const float e = __expf(rv[0] - m);
        tv[k] = e; tix[k] = ri[0];
        E8 += e;
        if (tid == 0) sh[ri[0]] = -1e30f;
        __syncthreads();
    }

    if (tid == 0) {
        const float inv = 1.0f / (E8 + 1e-6f * Z);
        for (int k = 0; k < KNN; k++) {
            d_TopV[row * KNN + k] = tv[k] * inv;
            d_TopI[row * KNN + k] = tix[k];
        }
    }
}

// ============================================================================
// Output: zero then symmetric sparse scatter (0.5*(A + A^T), <=16 nnz/row).
// ============================================================================
__global__ void zero_kernel(float* __restrict__ out)
{
    const size_t i = (size_t)blockIdx.x * blockDim.x + threadIdx.x;
    ((float4*)out)[i] = make_float4(0.f, 0.f, 0.f, 0.f);
}

__global__ void scatter_kernel(float* __restrict__ out)
{
    const int t = blockIdx.x * blockDim.x + threadIdx.x;
    if (t >= ROWS * KNN) return;
    const int row = t / KNN;
    const int b = row >> 12;
    const int i = row & (NN - 1);
    const int j = d_TopI[t];
    const float v = 0.5f * d_TopV[t];
    float* base = out + (size_t)b * NN * NN;
    atomicAdd(base + (size_t)i * NN + j, v);
    atomicAdd(base + (size_t)j * NN + i, v);
}

// ============================================================================
extern "C" void kernel_launch(void* const* d_in, const int* in_sizes, int n_in,
                              void* d_out, int out_size)
{
    const float* x  = (const float*)d_in[0];   // [4,4096,256]
    const float* Wq = (const float*)d_in[1];   // [256,256]
    const float* bq = (const float*)d_in[2];   // [256]
    const float* Wk = (const float*)d_in[3];   // [256,256]
    const float* bk = (const float*)d_in[4];   // [256]
    float* out = (float*)d_out;

    void *pq, *pk, *ps;
    cudaGetSymbolAddress(&pq, d_Qg);
    cudaGetSymbolAddress(&pk, d_Kg);
    cudaGetSymbolAddress(&ps, d_Sg);
    float* Qg = (float*)pq;
    float* Kg = (float*)pk;
    float* Sg = (float*)ps;

    // 1) projections: Q = x @ Wq^T + bq ; K = x @ Wk^T + bk  (M=16384,N=256,K=256)
    dim3 gProj(HID / BN, ROWS / BM, 1);   // (2,128,1)
    sgemm_tn_kernel<<<gProj, 256>>>(x, Wq, Qg, HID, HID, 0, 0, 0, bq, 1.0f);
    sgemm_tn_kernel<<<gProj, 256>>>(x, Wk, Kg, HID, HID, 0, 0, 0, bk, 1.0f);

    // 2) scores: S[b] = Q[b] @ K[b]^T / sqrt(256)   (per-batch 4096x4096x256)
    dim3 gS(NN / BN, NN / BM, BATCH);     // (32,32,4)
    sgemm_tn_kernel<<<gS, 256>>>(Qg, Kg, Sg, NN, HID,
                                 (long)NN * HID, (long)NN * HID, (long)NN * NN,
                                 nullptr, 0.0625f);

    // 3) per-row softmax stats + top-8
    rowtopk_kernel<<<ROWS, 256>>>();

    // 4) zero output, 5) symmetric sparse scatter
    zero_kernel<<<((size_t)BATCH * NN * NN / 4) / 256, 256>>>(out);
    scatter_kernel<<<(ROWS * KNN + 255) / 256, 256>>>(out);
}